// round 4
// baseline (speedup 1.0000x reference)
#include <cuda_runtime.h>
#include <cuda_bf16.h>
#include <cstdint>

// ---------------------------------------------------------------------------
// SPMoEAdaptor: out = moe_b(moe_a(x)) + x
//   moe(x) = sum_e softmax(x@Wg)[:,e] * ((x - b_e) @ W_e)
//          = sum_e (g_e * x) @ W_e  -  sum_e g_e * (b_e @ W_e)
// R3: no X/h smem tiles at all. X fragments loaded straight from gmem (fp32 ->
// bf16 packs); gate-A logits computed from the same loads via quad shfl;
// layer-B A-fragments repacked directly from layer-A C-fragments (layout
// identity). smem holds only the two pre-swizzled weight images + consts
// (68KB) -> 3 CTAs/SM; warps fully independent inside the tile loop.
// ---------------------------------------------------------------------------

namespace {
constexpr int MT = 128;                 // tokens per tile (32 per warp)

// dynamic smem layout (bytes)
constexpr int SM_WA  = 0;               // 256 rows x 128B bf16 (layer A weights, swizzled)
constexpr int SM_WB  = 32768;           // layer B weights
constexpr int SM_WGA = 65536;           // 64 x float4 (w_gate_a as [d][e])
constexpr int SM_WGB = 66560;
constexpr int SM_CA  = 67584;           // 64 x float4 (c_a as [f][e])
constexpr int SM_CB  = 68608;
constexpr int SMEM_TOTAL = 69632;       // 68KB -> 3 CTAs/SM

constexpr int GRID = 444;               // 148 SMs * 3 CTAs/SM
}

// device-global scratch (allocation-free rule)
__device__ __align__(16) __nv_bfloat16 g_wswz[2][256 * 64]; // pre-swizzled bf16 W images
__device__ __align__(16) float g_c[2][64 * 4];              // c[L][f*4+e] = (b_e @ W_e)[f]

// ------------------------------- helpers ----------------------------------

__device__ __forceinline__ uint32_t smem_u32(const void* p) {
    uint32_t a;
    asm("{ .reg .u64 t; cvta.to.shared.u64 t, %1; cvt.u32.u64 %0, t; }" : "=r"(a) : "l"(p));
    return a;
}

__device__ __forceinline__ void ldsm_x4_t(uint32_t* r, uint32_t addr) {
    asm volatile("ldmatrix.sync.aligned.m8n8.x4.trans.shared.b16 {%0,%1,%2,%3}, [%4];"
                 : "=r"(r[0]), "=r"(r[1]), "=r"(r[2]), "=r"(r[3]) : "r"(addr));
}

__device__ __forceinline__ void mma_bf16(float* d, const uint32_t* a,
                                         uint32_t b0, uint32_t b1) {
    asm volatile("mma.sync.aligned.m16n8k16.row.col.f32.bf16.bf16.f32 "
                 "{%0,%1,%2,%3}, {%4,%5,%6,%7}, {%8,%9}, {%0,%1,%2,%3};"
                 : "+f"(d[0]), "+f"(d[1]), "+f"(d[2]), "+f"(d[3])
                 : "r"(a[0]), "r"(a[1]), "r"(a[2]), "r"(a[3]), "r"(b0), "r"(b1));
}

__device__ __forceinline__ uint32_t pack_bf2(float lo, float hi) {
    __nv_bfloat162 t = __floats2bfloat162_rn(lo, hi);
    return *reinterpret_cast<uint32_t*>(&t);
}

__device__ __forceinline__ uint32_t bf2bcast(float v) { return pack_bf2(v, v); }

__device__ __forceinline__ uint32_t hmul2u(uint32_t a, uint32_t b) {
    __nv_bfloat162 r = __hmul2(*reinterpret_cast<__nv_bfloat162*>(&a),
                               *reinterpret_cast<__nv_bfloat162*>(&b));
    return *reinterpret_cast<uint32_t*>(&r);
}

__device__ __forceinline__ float dot4(float4 a, float4 b) {
    return a.x * b.x + a.y * b.y + a.z * b.z + a.w * b.w;
}

__device__ __forceinline__ float4 softmax4(float4 l) {
    float mx = fmaxf(fmaxf(l.x, l.y), fmaxf(l.z, l.w));
    float e0 = __expf(l.x - mx), e1 = __expf(l.y - mx),
          e2 = __expf(l.z - mx), e3 = __expf(l.w - mx);
    float inv = 1.f / (e0 + e1 + e2 + e3);
    return make_float4(e0 * inv, e1 * inv, e2 * inv, e3 * inv);
}

__device__ __forceinline__ void shfl_reduce_quad(float4& v) {
    v.x += __shfl_xor_sync(0xffffffffu, v.x, 1);
    v.y += __shfl_xor_sync(0xffffffffu, v.y, 1);
    v.z += __shfl_xor_sync(0xffffffffu, v.z, 1);
    v.w += __shfl_xor_sync(0xffffffffu, v.w, 1);
    v.x += __shfl_xor_sync(0xffffffffu, v.x, 2);
    v.y += __shfl_xor_sync(0xffffffffu, v.y, 2);
    v.z += __shfl_xor_sync(0xffffffffu, v.z, 2);
    v.w += __shfl_xor_sync(0xffffffffu, v.w, 2);
}

// one MoE GEMM layer: acc[2][8][4] += sum over e,kt of (g_e o A_frag) @ W_frag
__device__ __forceinline__ void run_layer(float acc[2][8][4],
                                          const uint32_t xf[2][4][4],
                                          const uint32_t g2[4][2][2],
                                          uint32_t wbase, int lane) {
    const int lr = lane & 15;
    const int hi = lane >> 4;
    const int l7 = lane & 7;
    #pragma unroll
    for (int e = 0; e < 4; e++) {
        #pragma unroll
        for (int kt = 0; kt < 4; kt++) {
            uint32_t a[2][4];
            #pragma unroll
            for (int m = 0; m < 2; m++) {
                a[m][0] = hmul2u(xf[m][kt][0], g2[e][m][0]);
                a[m][1] = hmul2u(xf[m][kt][1], g2[e][m][1]);
                a[m][2] = hmul2u(xf[m][kt][2], g2[e][m][0]);
                a[m][3] = hmul2u(xf[m][kt][3], g2[e][m][1]);
            }
            const uint32_t r = (uint32_t)(e * 64 + kt * 16 + lr);
            #pragma unroll
            for (int np = 0; np < 4; np++) {
                uint32_t chunk = (uint32_t)((np * 2 + hi) ^ l7);
                uint32_t b[4];
                ldsm_x4_t(b, wbase + r * 128u + chunk * 16u);
                #pragma unroll
                for (int m = 0; m < 2; m++) {
                    mma_bf16(acc[m][2 * np],     a[m], b[0], b[1]);
                    mma_bf16(acc[m][2 * np + 1], a[m], b[2], b[3]);
                }
            }
        }
    }
}

// ------------------------------- prep kernel ------------------------------

__global__ void prep_kernel(const float* __restrict__ wea, const float* __restrict__ bea,
                            const float* __restrict__ web, const float* __restrict__ beb) {
    int idx = blockIdx.x * blockDim.x + threadIdx.x;
    if (idx < 2 * 4 * 64 * 64) {
        int L = idx >> 14;
        int r = idx & 16383;
        int e = r >> 12;
        int d = (r >> 6) & 63;
        int f = r & 63;
        const float* w = L ? web : wea;
        float v = w[(e * 64 + d) * 64 + f];
        int row = e * 64 + d;                       // K-index row
        int chunk = (f >> 3) ^ (d & 7);             // 16B-chunk XOR swizzle
        g_wswz[L][row * 64 + chunk * 8 + (f & 7)] = __float2bfloat16(v);
    }
    if (idx < 2 * 4 * 64) {
        int L = idx >> 8;
        int e = (idx >> 6) & 3;
        int f = idx & 63;
        const float* w = L ? web : wea;
        const float* b = L ? beb : bea;
        float s = 0.f;
        for (int d = 0; d < 64; d++)
            s += b[e * 64 + d] * w[(e * 64 + d) * 64 + f];
        g_c[L][f * 4 + e] = s;
    }
}

// ------------------------------- main kernel ------------------------------

__global__ void __launch_bounds__(128, 3)
moe_kernel(const float* __restrict__ x,
           const float* __restrict__ wg_a,
           const float* __restrict__ wg_b,
           float* __restrict__ out,
           int ntiles) {
    extern __shared__ char smem[];
    const uint32_t sb = smem_u32(smem);
    const int tid  = threadIdx.x;
    const int lane = tid & 31;
    const int warp = tid >> 5;
    const int rbase = warp * 32;

    // ---- one-time cooperative weight copies ----
    {
        const uint4* s0 = reinterpret_cast<const uint4*>(g_wswz[0]);
        const uint4* s1 = reinterpret_cast<const uint4*>(g_wswz[1]);
        uint4* dA = reinterpret_cast<uint4*>(smem + SM_WA);
        uint4* dB = reinterpret_cast<uint4*>(smem + SM_WB);
        #pragma unroll
        for (int i = tid; i < 2048; i += 128) { dA[i] = s0[i]; dB[i] = s1[i]; }
        float* wga_s = reinterpret_cast<float*>(smem + SM_WGA);
        float* wgb_s = reinterpret_cast<float*>(smem + SM_WGB);
        float* ca_s  = reinterpret_cast<float*>(smem + SM_CA);
        float* cb_s  = reinterpret_cast<float*>(smem + SM_CB);
        #pragma unroll
        for (int i = tid; i < 256; i += 128) {
            wga_s[i] = wg_a[i]; wgb_s[i] = wg_b[i];
            ca_s[i]  = g_c[0][i]; cb_s[i] = g_c[1][i];
        }
    }
    __syncthreads();

    const float4* WGA4 = reinterpret_cast<const float4*>(smem + SM_WGA);
    const float4* WGB4 = reinterpret_cast<const float4*>(smem + SM_WGB);
    const float4* CA4  = reinterpret_cast<const float4*>(smem + SM_CA);
    const float4* CB4  = reinterpret_cast<const float4*>(smem + SM_CB);

    const int ql = lane & 3;      // quad lane -> column group
    const int qr = lane >> 2;     // row within 8-row group

    for (int tile = blockIdx.x; tile < ntiles; tile += gridDim.x) {
        const size_t tokbase = (size_t)tile * MT;

        // ---- X fragments straight from gmem + gate-A partial logits ----
        uint32_t xf[2][4][4];
        float4 lg[2][2];
        #pragma unroll
        for (int m = 0; m < 2; m++) {
            lg[m][0] = make_float4(0.f, 0.f, 0.f, 0.f);
            lg[m][1] = make_float4(0.f, 0.f, 0.f, 0.f);
            const size_t r = tokbase + (size_t)(rbase + m * 16 + qr);
            const float* xr0 = x + r * 64;
            const float* xr8 = xr0 + 8 * 64;
            #pragma unroll
            for (int kt = 0; kt < 4; kt++) {
                const int c0 = kt * 16 + ql * 2;
                float2 f0 = *reinterpret_cast<const float2*>(xr0 + c0);
                float2 f1 = *reinterpret_cast<const float2*>(xr8 + c0);
                float2 f2 = *reinterpret_cast<const float2*>(xr0 + c0 + 8);
                float2 f3 = *reinterpret_cast<const float2*>(xr8 + c0 + 8);
                xf[m][kt][0] = pack_bf2(f0.x, f0.y);
                xf[m][kt][1] = pack_bf2(f1.x, f1.y);
                xf[m][kt][2] = pack_bf2(f2.x, f2.y);
                xf[m][kt][3] = pack_bf2(f3.x, f3.y);
                float4 w0 = WGA4[c0], w1 = WGA4[c0 + 1];
                float4 w2 = WGA4[c0 + 8], w3 = WGA4[c0 + 9];
                lg[m][0].x += f0.x*w0.x + f0.y*w1.x + f2.x*w2.x + f2.y*w3.x;
                lg[m][0].y += f0.x*w0.y + f0.y*w1.y + f2.x*w2.y + f2.y*w3.y;
                lg[m][0].z += f0.x*w0.z + f0.y*w1.z + f2.x*w2.z + f2.y*w3.z;
                lg[m][0].w += f0.x*w0.w + f0.y*w1.w + f2.x*w2.w + f2.y*w3.w;
                lg[m][1].x += f1.x*w0.x + f1.y*w1.x + f3.x*w2.x + f3.y*w3.x;
                lg[m][1].y += f1.x*w0.y + f1.y*w1.y + f3.x*w2.y + f3.y*w3.y;
                lg[m][1].z += f1.x*w0.z + f1.y*w1.z + f3.x*w2.z + f3.y*w3.z;
                lg[m][1].w += f1.x*w0.w + f1.y*w1.w + f3.x*w2.w + f3.y*w3.w;
            }
        }

        // ---- gates A: quad-reduce + softmax ----
        float4 gAf[2][2];
        uint32_t gA2[4][2][2];
        #pragma unroll
        for (int m = 0; m < 2; m++)
            #pragma unroll
            for (int h = 0; h < 2; h++) {
                shfl_reduce_quad(lg[m][h]);
                float4 g = softmax4(lg[m][h]);
                gAf[m][h] = g;
                gA2[0][m][h] = bf2bcast(g.x); gA2[1][m][h] = bf2bcast(g.y);
                gA2[2][m][h] = bf2bcast(g.z); gA2[3][m][h] = bf2bcast(g.w);
            }

        // ---- layer A GEMM ----
        float acc[2][8][4];
        #pragma unroll
        for (int m = 0; m < 2; m++)
            #pragma unroll
            for (int n = 0; n < 8; n++)
                #pragma unroll
                for (int k = 0; k < 4; k++) acc[m][n][k] = 0.f;

        run_layer(acc, xf, gA2, sb + SM_WA, lane);

        // ---- fold bias: h = acc - sum_e g_e c_a ----
        #pragma unroll
        for (int m = 0; m < 2; m++)
            #pragma unroll
            for (int n = 0; n < 8; n++) {
                int c = n * 8 + ql * 2;
                float4 c0 = CA4[c], c1 = CA4[c + 1];
                acc[m][n][0] -= dot4(gAf[m][0], c0);
                acc[m][n][1] -= dot4(gAf[m][0], c1);
                acc[m][n][2] -= dot4(gAf[m][1], c0);
                acc[m][n][3] -= dot4(gAf[m][1], c1);
            }

        // ---- gates B partial logits from fp32 h (register-resident) ----
        float4 lgB[2][2];
        #pragma unroll
        for (int m = 0; m < 2; m++) { lgB[m][0] = make_float4(0.f,0.f,0.f,0.f);
                                      lgB[m][1] = make_float4(0.f,0.f,0.f,0.f); }
        #pragma unroll
        for (int n = 0; n < 8; n++) {
            int c = n * 8 + ql * 2;
            float4 w0 = WGB4[c], w1 = WGB4[c + 1];
            #pragma unroll
            for (int m = 0; m < 2; m++)
                #pragma unroll
                for (int h = 0; h < 2; h++) {
                    float v0 = acc[m][n][h * 2], v1 = acc[m][n][h * 2 + 1];
                    lgB[m][h].x += v0 * w0.x + v1 * w1.x;
                    lgB[m][h].y += v0 * w0.y + v1 * w1.y;
                    lgB[m][h].z += v0 * w0.z + v1 * w1.z;
                    lgB[m][h].w += v0 * w0.w + v1 * w1.w;
                }
        }
        float4 gBf[2][2];
        uint32_t gB2[4][2][2];
        #pragma unroll
        for (int m = 0; m < 2; m++)
            #pragma unroll
            for (int h = 0; h < 2; h++) {
                shfl_reduce_quad(lgB[m][h]);
                float4 g = softmax4(lgB[m][h]);
                gBf[m][h] = g;
                gB2[0][m][h] = bf2bcast(g.x); gB2[1][m][h] = bf2bcast(g.y);
                gB2[2][m][h] = bf2bcast(g.z); gB2[3][m][h] = bf2bcast(g.w);
            }

        // ---- repack h: C-fragment layout == A-fragment layout (per kt) ----
        #pragma unroll
        for (int m = 0; m < 2; m++)
            #pragma unroll
            for (int kt = 0; kt < 4; kt++) {
                xf[m][kt][0] = pack_bf2(acc[m][2*kt][0],   acc[m][2*kt][1]);
                xf[m][kt][1] = pack_bf2(acc[m][2*kt][2],   acc[m][2*kt][3]);
                xf[m][kt][2] = pack_bf2(acc[m][2*kt+1][0], acc[m][2*kt+1][1]);
                xf[m][kt][3] = pack_bf2(acc[m][2*kt+1][2], acc[m][2*kt+1][3]);
            }

        // ---- layer B GEMM ----
        #pragma unroll
        for (int m = 0; m < 2; m++)
            #pragma unroll
            for (int n = 0; n < 8; n++)
                #pragma unroll
                for (int k = 0; k < 4; k++) acc[m][n][k] = 0.f;

        run_layer(acc, xf, gB2, sb + SM_WB, lane);

        // ---- epilogue: out = acc - sum_e g_e c_b + x (fp32 residual) ----
        #pragma unroll
        for (int m = 0; m < 2; m++) {
            size_t rl = tokbase + (size_t)(rbase + m * 16 + qr);
            size_t rh = rl + 8;
            #pragma unroll
            for (int n = 0; n < 8; n++) {
                int c = n * 8 + ql * 2;
                float4 c0 = CB4[c], c1 = CB4[c + 1];
                float2 xl = *reinterpret_cast<const float2*>(x + rl * 64 + c);
                float2 xh = *reinterpret_cast<const float2*>(x + rh * 64 + c);
                float2 ol, oh;
                ol.x = acc[m][n][0] - dot4(gBf[m][0], c0) + xl.x;
                ol.y = acc[m][n][1] - dot4(gBf[m][0], c1) + xl.y;
                oh.x = acc[m][n][2] - dot4(gBf[m][1], c0) + xh.x;
                oh.y = acc[m][n][3] - dot4(gBf[m][1], c1) + xh.y;
                *reinterpret_cast<float2*>(out + rl * 64 + c) = ol;
                *reinterpret_cast<float2*>(out + rh * 64 + c) = oh;
            }
        }
    }
}

// ------------------------------- launch -----------------------------------

extern "C" void kernel_launch(void* const* d_in, const int* in_sizes, int n_in,
                              void* d_out, int out_size) {
    const float* x   = (const float*)d_in[0];
    const float* wga = (const float*)d_in[1];
    const float* wea = (const float*)d_in[2];
    const float* bea = (const float*)d_in[3];
    const float* wgb = (const float*)d_in[4];
    const float* web = (const float*)d_in[5];
    const float* beb = (const float*)d_in[6];
    float* out = (float*)d_out;

    const int ntok   = in_sizes[0] / 64;
    const int ntiles = ntok / MT;

    prep_kernel<<<64, 512>>>(wea, bea, web, beb);

    cudaFuncSetAttribute(moe_kernel, cudaFuncAttributeMaxDynamicSharedMemorySize, SMEM_TOTAL);
    int grid = ntiles < GRID ? ntiles : GRID;
    moe_kernel<<<grid, 128, SMEM_TOTAL>>>(x, wga, wgb, out, ntiles);
}

// round 5
// speedup vs baseline: 1.2561x; 1.2561x over previous
#include <cuda_runtime.h>
#include <cuda_bf16.h>
#include <cstdint>

// ---------------------------------------------------------------------------
// SPMoEAdaptor: out = moe_b(moe_a(x)) + x
//   moe(x) = sum_e softmax(x@Wg)[:,e] * ((x - b_e) @ W_e)
//          = sum_e (g_e * x) @ W_e  -  sum_e g_e * (b_e @ W_e)
// R4: gate logits computed on the tensor core (tiny MMAs with register-
// resident Wg fragments, single shfl_xor(1) gather). Bias folded into acc
// init pre-GEMM; residual+bias folded into layer-B acc init so the x re-read
// overlaps GEMM B; epilogue is pure streaming stores. L2 prefetch of the
// next tile's x. 3 CTAs/SM, warps fully independent in the tile loop.
// ---------------------------------------------------------------------------

namespace {
constexpr int MT = 128;                 // tokens per tile (32 per warp)

// dynamic smem layout (bytes)
constexpr int SM_WA  = 0;               // 256 rows x 128B bf16 (layer A weights, swizzled)
constexpr int SM_WB  = 32768;           // layer B weights
constexpr int SM_WGA = 65536;           // 64 x float4 (w_gate_a as [d][e])
constexpr int SM_WGB = 66560;
constexpr int SM_CA  = 67584;           // 64 x float4 (c_a as [f][e])
constexpr int SM_CB  = 68608;
constexpr int SMEM_TOTAL = 69632;       // 68KB -> 3 CTAs/SM

constexpr int GRID = 444;               // 148 SMs * 3 CTAs/SM
}

// device-global scratch (allocation-free rule)
__device__ __align__(16) __nv_bfloat16 g_wswz[2][256 * 64]; // pre-swizzled bf16 W images
__device__ __align__(16) float g_c[2][64 * 4];              // c[L][f*4+e] = (b_e @ W_e)[f]

// ------------------------------- helpers ----------------------------------

__device__ __forceinline__ uint32_t smem_u32(const void* p) {
    uint32_t a;
    asm("{ .reg .u64 t; cvta.to.shared.u64 t, %1; cvt.u32.u64 %0, t; }" : "=r"(a) : "l"(p));
    return a;
}

__device__ __forceinline__ void ldsm_x4_t(uint32_t* r, uint32_t addr) {
    asm volatile("ldmatrix.sync.aligned.m8n8.x4.trans.shared.b16 {%0,%1,%2,%3}, [%4];"
                 : "=r"(r[0]), "=r"(r[1]), "=r"(r[2]), "=r"(r[3]) : "r"(addr));
}

__device__ __forceinline__ void mma_bf16(float* d, const uint32_t* a,
                                         uint32_t b0, uint32_t b1) {
    asm volatile("mma.sync.aligned.m16n8k16.row.col.f32.bf16.bf16.f32 "
                 "{%0,%1,%2,%3}, {%4,%5,%6,%7}, {%8,%9}, {%0,%1,%2,%3};"
                 : "+f"(d[0]), "+f"(d[1]), "+f"(d[2]), "+f"(d[3])
                 : "r"(a[0]), "r"(a[1]), "r"(a[2]), "r"(a[3]), "r"(b0), "r"(b1));
}

__device__ __forceinline__ uint32_t pack_bf2(float lo, float hi) {
    __nv_bfloat162 t = __floats2bfloat162_rn(lo, hi);
    return *reinterpret_cast<uint32_t*>(&t);
}

__device__ __forceinline__ uint32_t bf2bcast(float v) { return pack_bf2(v, v); }

__device__ __forceinline__ uint32_t hmul2u(uint32_t a, uint32_t b) {
    __nv_bfloat162 r = __hmul2(*reinterpret_cast<__nv_bfloat162*>(&a),
                               *reinterpret_cast<__nv_bfloat162*>(&b));
    return *reinterpret_cast<uint32_t*>(&r);
}

__device__ __forceinline__ float dot4(float4 a, float4 b) {
    return a.x * b.x + a.y * b.y + a.z * b.z + a.w * b.w;
}

__device__ __forceinline__ float4 softmax4(float4 l) {
    float mx = fmaxf(fmaxf(l.x, l.y), fmaxf(l.z, l.w));
    float e0 = __expf(l.x - mx), e1 = __expf(l.y - mx),
          e2 = __expf(l.z - mx), e3 = __expf(l.w - mx);
    float inv = 1.f / (e0 + e1 + e2 + e3);
    return make_float4(e0 * inv, e1 * inv, e2 * inv, e3 * inv);
}

// one MoE GEMM layer: acc[2][8][4] += sum over e,kt of (g_e o A_frag) @ W_frag
__device__ __forceinline__ void run_layer(float acc[2][8][4],
                                          const uint32_t xf[2][4][4],
                                          const uint32_t g2[4][2][2],
                                          uint32_t wbase, int lane) {
    const int lr = lane & 15;
    const int hi = lane >> 4;
    const int l7 = lane & 7;
    #pragma unroll
    for (int e = 0; e < 4; e++) {
        #pragma unroll
        for (int kt = 0; kt < 4; kt++) {
            uint32_t a[2][4];
            #pragma unroll
            for (int m = 0; m < 2; m++) {
                a[m][0] = hmul2u(xf[m][kt][0], g2[e][m][0]);
                a[m][1] = hmul2u(xf[m][kt][1], g2[e][m][1]);
                a[m][2] = hmul2u(xf[m][kt][2], g2[e][m][0]);
                a[m][3] = hmul2u(xf[m][kt][3], g2[e][m][1]);
            }
            const uint32_t r = (uint32_t)(e * 64 + kt * 16 + lr);
            #pragma unroll
            for (int np = 0; np < 4; np++) {
                uint32_t chunk = (uint32_t)((np * 2 + hi) ^ l7);
                uint32_t b[4];
                ldsm_x4_t(b, wbase + r * 128u + chunk * 16u);
                #pragma unroll
                for (int m = 0; m < 2; m++) {
                    mma_bf16(acc[m][2 * np],     a[m], b[0], b[1]);
                    mma_bf16(acc[m][2 * np + 1], a[m], b[2], b[3]);
                }
            }
        }
    }
}

// gates from A-fragments via tensor core: logits = frag @ Wg (Wg frags const).
// Output cols 0..3 = experts; cols 4..7 duplicate them (e = qr&3), so a single
// shfl_xor(1) completes the per-row gather.
__device__ __forceinline__ void gates_from_frags(const uint32_t xf[4][4],
                                                 const uint32_t* wg0,
                                                 const uint32_t* wg1,
                                                 int ql,
                                                 float4 gf[2],
                                                 uint32_t g2[4][2]) {
    float l[4] = {0.f, 0.f, 0.f, 0.f};
    #pragma unroll
    for (int kt = 0; kt < 4; kt++)
        mma_bf16(l, xf[kt], wg0[kt], wg1[kt]);
    float r0 = __shfl_xor_sync(0xffffffffu, l[0], 1);
    float r1 = __shfl_xor_sync(0xffffffffu, l[1], 1);
    float r2 = __shfl_xor_sync(0xffffffffu, l[2], 1);
    float r3 = __shfl_xor_sync(0xffffffffu, l[3], 1);
    bool even = (ql & 1) == 0;
    float4 La = even ? make_float4(l[0], l[1], r0, r1)
                     : make_float4(r0, r1, l[0], l[1]);
    float4 Lb = even ? make_float4(l[2], l[3], r2, r3)
                     : make_float4(r2, r3, l[2], l[3]);
    float4 ga = softmax4(La);
    float4 gb = softmax4(Lb);
    gf[0] = ga; gf[1] = gb;
    g2[0][0] = bf2bcast(ga.x); g2[1][0] = bf2bcast(ga.y);
    g2[2][0] = bf2bcast(ga.z); g2[3][0] = bf2bcast(ga.w);
    g2[0][1] = bf2bcast(gb.x); g2[1][1] = bf2bcast(gb.y);
    g2[2][1] = bf2bcast(gb.z); g2[3][1] = bf2bcast(gb.w);
}

// ------------------------------- prep kernel ------------------------------

__global__ void prep_kernel(const float* __restrict__ wea, const float* __restrict__ bea,
                            const float* __restrict__ web, const float* __restrict__ beb) {
    int idx = blockIdx.x * blockDim.x + threadIdx.x;
    if (idx < 2 * 4 * 64 * 64) {
        int L = idx >> 14;
        int r = idx & 16383;
        int e = r >> 12;
        int d = (r >> 6) & 63;
        int f = r & 63;
        const float* w = L ? web : wea;
        float v = w[(e * 64 + d) * 64 + f];
        int row = e * 64 + d;                       // K-index row
        int chunk = (f >> 3) ^ (d & 7);             // 16B-chunk XOR swizzle
        g_wswz[L][row * 64 + chunk * 8 + (f & 7)] = __float2bfloat16(v);
    }
    if (idx < 2 * 4 * 64) {
        int L = idx >> 8;
        int e = (idx >> 6) & 3;
        int f = idx & 63;
        const float* w = L ? web : wea;
        const float* b = L ? beb : bea;
        float s = 0.f;
        for (int d = 0; d < 64; d++)
            s += b[e * 64 + d] * w[(e * 64 + d) * 64 + f];
        g_c[L][f * 4 + e] = s;
    }
}

// ------------------------------- main kernel ------------------------------

__global__ void __launch_bounds__(128, 3)
moe_kernel(const float* __restrict__ x,
           const float* __restrict__ wg_a,
           const float* __restrict__ wg_b,
           float* __restrict__ out,
           int ntiles) {
    extern __shared__ char smem[];
    const uint32_t sb = smem_u32(smem);
    const int tid  = threadIdx.x;
    const int lane = tid & 31;
    const int warp = tid >> 5;
    const int rbase = warp * 32;

    // ---- one-time cooperative weight copies ----
    {
        const uint4* s0 = reinterpret_cast<const uint4*>(g_wswz[0]);
        const uint4* s1 = reinterpret_cast<const uint4*>(g_wswz[1]);
        uint4* dA = reinterpret_cast<uint4*>(smem + SM_WA);
        uint4* dB = reinterpret_cast<uint4*>(smem + SM_WB);
        #pragma unroll
        for (int i = tid; i < 2048; i += 128) { dA[i] = s0[i]; dB[i] = s1[i]; }
        float* wga_s = reinterpret_cast<float*>(smem + SM_WGA);
        float* wgb_s = reinterpret_cast<float*>(smem + SM_WGB);
        float* ca_s  = reinterpret_cast<float*>(smem + SM_CA);
        float* cb_s  = reinterpret_cast<float*>(smem + SM_CB);
        #pragma unroll
        for (int i = tid; i < 256; i += 128) {
            wga_s[i] = wg_a[i]; wgb_s[i] = wg_b[i];
            ca_s[i]  = g_c[0][i]; cb_s[i] = g_c[1][i];
        }
    }
    __syncthreads();

    const float4* CA4  = reinterpret_cast<const float4*>(smem + SM_CA);
    const float4* CB4  = reinterpret_cast<const float4*>(smem + SM_CB);

    const int ql = lane & 3;      // quad lane -> column group
    const int qr = lane >> 2;     // row within 8-row group

    // ---- register-resident Wg B-fragments (tile-invariant) ----
    uint32_t wgA0[4], wgA1[4], wgB0[4], wgB1[4];
    {
        const float* WGAf = reinterpret_cast<const float*>(smem + SM_WGA);
        const float* WGBf = reinterpret_cast<const float*>(smem + SM_WGB);
        const int e4 = qr & 3;
        #pragma unroll
        for (int kt = 0; kt < 4; kt++) {
            int d0 = kt * 16 + 2 * ql;
            wgA0[kt] = pack_bf2(WGAf[d0 * 4 + e4],       WGAf[(d0 + 1) * 4 + e4]);
            wgA1[kt] = pack_bf2(WGAf[(d0 + 8) * 4 + e4], WGAf[(d0 + 9) * 4 + e4]);
            wgB0[kt] = pack_bf2(WGBf[d0 * 4 + e4],       WGBf[(d0 + 1) * 4 + e4]);
            wgB1[kt] = pack_bf2(WGBf[(d0 + 8) * 4 + e4], WGBf[(d0 + 9) * 4 + e4]);
        }
    }

    for (int tile = blockIdx.x; tile < ntiles; tile += gridDim.x) {
        const size_t tokbase = (size_t)tile * MT;

        // ---- X fragments straight from gmem ----
        uint32_t xf[2][4][4];
        #pragma unroll
        for (int m = 0; m < 2; m++) {
            const size_t r = tokbase + (size_t)(rbase + m * 16 + qr);
            const float* xr0 = x + r * 64;
            const float* xr8 = xr0 + 8 * 64;
            #pragma unroll
            for (int kt = 0; kt < 4; kt++) {
                const int c0 = kt * 16 + ql * 2;
                float2 f0 = *reinterpret_cast<const float2*>(xr0 + c0);
                float2 f1 = *reinterpret_cast<const float2*>(xr8 + c0);
                float2 f2 = *reinterpret_cast<const float2*>(xr0 + c0 + 8);
                float2 f3 = *reinterpret_cast<const float2*>(xr8 + c0 + 8);
                xf[m][kt][0] = pack_bf2(f0.x, f0.y);
                xf[m][kt][1] = pack_bf2(f1.x, f1.y);
                xf[m][kt][2] = pack_bf2(f2.x, f2.y);
                xf[m][kt][3] = pack_bf2(f3.x, f3.y);
            }
        }

        // ---- gates A on tensor core ----
        float4 gAf[2][2];
        uint32_t gA2[4][2][2];
        {
            float4 gf[2]; uint32_t g2c[4][2];
            #pragma unroll
            for (int m = 0; m < 2; m++) {
                gates_from_frags(xf[m], wgA0, wgA1, ql, gf, g2c);
                gAf[m][0] = gf[0]; gAf[m][1] = gf[1];
                #pragma unroll
                for (int e = 0; e < 4; e++) {
                    gA2[e][m][0] = g2c[e][0]; gA2[e][m][1] = g2c[e][1];
                }
            }
        }

        // ---- layer A: acc init = -sum_e g_e c_a (bias), then GEMM ----
        float acc[2][8][4];
        #pragma unroll
        for (int m = 0; m < 2; m++)
            #pragma unroll
            for (int n = 0; n < 8; n++) {
                int c = n * 8 + ql * 2;
                float4 c0 = CA4[c], c1 = CA4[c + 1];
                acc[m][n][0] = -dot4(gAf[m][0], c0);
                acc[m][n][1] = -dot4(gAf[m][0], c1);
                acc[m][n][2] = -dot4(gAf[m][1], c0);
                acc[m][n][3] = -dot4(gAf[m][1], c1);
            }

        run_layer(acc, xf, gA2, sb + SM_WA, lane);

        // ---- repack h: C-fragment layout == A-fragment layout (per kt) ----
        #pragma unroll
        for (int m = 0; m < 2; m++)
            #pragma unroll
            for (int kt = 0; kt < 4; kt++) {
                xf[m][kt][0] = pack_bf2(acc[m][2*kt][0],   acc[m][2*kt][1]);
                xf[m][kt][1] = pack_bf2(acc[m][2*kt][2],   acc[m][2*kt][3]);
                xf[m][kt][2] = pack_bf2(acc[m][2*kt+1][0], acc[m][2*kt+1][1]);
                xf[m][kt][3] = pack_bf2(acc[m][2*kt+1][2], acc[m][2*kt+1][3]);
            }

        // ---- prefetch next tile's x into L2 (8KB per warp) ----
        if (tile + (int)gridDim.x < ntiles) {
            const char* p = reinterpret_cast<const char*>(
                x + (tokbase + (size_t)gridDim.x * MT + rbase) * 64) + lane * 256;
            asm volatile("prefetch.global.L2 [%0];" :: "l"(p));
            asm volatile("prefetch.global.L2 [%0];" :: "l"(p + 128));
        }

        // ---- gates B on tensor core ----
        float4 gBf[2][2];
        uint32_t gB2[4][2][2];
        {
            float4 gf[2]; uint32_t g2c[4][2];
            #pragma unroll
            for (int m = 0; m < 2; m++) {
                gates_from_frags(xf[m], wgB0, wgB1, ql, gf, g2c);
                gBf[m][0] = gf[0]; gBf[m][1] = gf[1];
                #pragma unroll
                for (int e = 0; e < 4; e++) {
                    gB2[e][m][0] = g2c[e][0]; gB2[e][m][1] = g2c[e][1];
                }
            }
        }

        // ---- layer B: acc init = x (residual) - sum_e g_e c_b, then GEMM ----
        #pragma unroll
        for (int m = 0; m < 2; m++) {
            const size_t rl = tokbase + (size_t)(rbase + m * 16 + qr);
            const size_t rh = rl + 8;
            #pragma unroll
            for (int n = 0; n < 8; n++) {
                int c = n * 8 + ql * 2;
                float4 c0 = CB4[c], c1 = CB4[c + 1];
                float2 xl = *reinterpret_cast<const float2*>(x + rl * 64 + c);
                float2 xh = *reinterpret_cast<const float2*>(x + rh * 64 + c);
                acc[m][n][0] = xl.x - dot4(gBf[m][0], c0);
                acc[m][n][1] = xl.y - dot4(gBf[m][0], c1);
                acc[m][n][2] = xh.x - dot4(gBf[m][1], c0);
                acc[m][n][3] = xh.y - dot4(gBf[m][1], c1);
            }
        }

        run_layer(acc, xf, gB2, sb + SM_WB, lane);

        // ---- epilogue: pure streaming stores ----
        #pragma unroll
        for (int m = 0; m < 2; m++) {
            const size_t rl = tokbase + (size_t)(rbase + m * 16 + qr);
            const size_t rh = rl + 8;
            #pragma unroll
            for (int n = 0; n < 8; n++) {
                int c = n * 8 + ql * 2;
                __stcs(reinterpret_cast<float2*>(out + rl * 64 + c),
                       make_float2(acc[m][n][0], acc[m][n][1]));
                __stcs(reinterpret_cast<float2*>(out + rh * 64 + c),
                       make_float2(acc[m][n][2], acc[m][n][3]));
            }
        }
    }
}

// ------------------------------- launch -----------------------------------

extern "C" void kernel_launch(void* const* d_in, const int* in_sizes, int n_in,
                              void* d_out, int out_size) {
    const float* x   = (const float*)d_in[0];
    const float* wga = (const float*)d_in[1];
    const float* wea = (const float*)d_in[2];
    const float* bea = (const float*)d_in[3];
    const float* wgb = (const float*)d_in[4];
    const float* web = (const float*)d_in[5];
    const float* beb = (const float*)d_in[6];
    float* out = (float*)d_out;

    const int ntok   = in_sizes[0] / 64;
    const int ntiles = ntok / MT;

    prep_kernel<<<64, 512>>>(wea, bea, web, beb);

    cudaFuncSetAttribute(moe_kernel, cudaFuncAttributeMaxDynamicSharedMemorySize, SMEM_TOTAL);
    int grid = ntiles < GRID ? ntiles : GRID;
    moe_kernel<<<grid, 128, SMEM_TOTAL>>>(x, wga, wgb, out, ntiles);
}